// round 12
// baseline (speedup 1.0000x reference)
#include <cuda_runtime.h>
#include <cuda_bf16.h>
#include <cstdint>

#define BATCH   16384
#define INF     256
#define GATES   1023
#define GPAD    1024
#define OUTF    128
#define LEAVES  1024

// ---------------- device scratch (static, no runtime allocation) ----------
// A-side layouts: [Ah | Al] (2K cols). B-side: [Bh | Bl] (2K cols).
__device__ __nv_bfloat16 g_xs[BATCH * 2 * INF];           // x'   [16384][512]
__device__ __nv_bfloat16 g_gws[GPAD * 2 * INF];           // gw'^T[1024][512] (row 1023 = 0)
__device__ __nv_bfloat16 g_zs[OUTF * 2 * LEAVES];         // z'   [128][2048]
__device__ __nv_bfloat16 g_ls[(size_t)BATCH * 2 * LEAVES];// leaf'[16384][2048]
__device__ float         g_gat[BATCH * GPAD];             // sigmoid gatings (fp32)

// ---------------- PTX helpers (sm_80-class, compile on compute_103) --------
__device__ __forceinline__ uint32_t smem_u32(const void* p) {
    uint32_t a;
    asm("{ .reg .u64 t; cvta.to.shared.u64 t, %1; cvt.u32.u64 %0, t; }"
        : "=r"(a) : "l"(p));
    return a;
}
#define CP16(dst, src) \
    asm volatile("cp.async.cg.shared.global [%0], [%1], 16;" \
                 :: "r"(dst), "l"(src) : "memory")
#define CPCOMMIT() asm volatile("cp.async.commit_group;" ::: "memory")
#define CPWAIT(n)  asm volatile("cp.async.wait_group %0;" :: "n"(n) : "memory")

__device__ __forceinline__ void ldm4(uint32_t* r, uint32_t addr) {
    asm volatile("ldmatrix.sync.aligned.m8n8.x4.shared.b16 {%0,%1,%2,%3}, [%4];"
                 : "=r"(r[0]), "=r"(r[1]), "=r"(r[2]), "=r"(r[3]) : "r"(addr));
}
__device__ __forceinline__ void mma16816(float* d, const uint32_t* a, const uint32_t* b) {
    asm volatile("mma.sync.aligned.m16n8k16.row.col.f32.bf16.bf16.f32 "
                 "{%0,%1,%2,%3}, {%4,%5,%6,%7}, {%8,%9}, {%0,%1,%2,%3};"
                 : "+f"(d[0]), "+f"(d[1]), "+f"(d[2]), "+f"(d[3])
                 : "r"(a[0]), "r"(a[1]), "r"(a[2]), "r"(a[3]),
                   "r"(b[0]), "r"(b[1]));
}
__device__ __forceinline__ void split2(float v, __nv_bfloat16& h, __nv_bfloat16& l) {
    h = __float2bfloat16(v);
    l = __float2bfloat16(v - __bfloat162float(h));
}

// ---------------- conversion kernels --------------------------------------
// x [16384,256] -> g_xs rows [Ah(0:256) | Al(256:512)]
__global__ __launch_bounds__(256) void conv_x(const float* __restrict__ x) {
    int i = blockIdx.x * 256 + threadIdx.x;           // float4 index
    int row = i >> 6, col = (i & 63) * 4;
    float4 v = reinterpret_cast<const float4*>(x)[i];
    __nv_bfloat16 h[4], l[4];
    split2(v.x, h[0], l[0]); split2(v.y, h[1], l[1]);
    split2(v.z, h[2], l[2]); split2(v.w, h[3], l[3]);
    __nv_bfloat16* r = &g_xs[(size_t)row * 512 + col];
    *reinterpret_cast<__nv_bfloat162*>(r)       = __nv_bfloat162{h[0], h[1]};
    *reinterpret_cast<__nv_bfloat162*>(r + 2)   = __nv_bfloat162{h[2], h[3]};
    *reinterpret_cast<__nv_bfloat162*>(r + 256) = __nv_bfloat162{l[0], l[1]};
    *reinterpret_cast<__nv_bfloat162*>(r + 258) = __nv_bfloat162{l[2], l[3]};
}
// gw [256,1023] -> gw'^T rows n: [Bh(0:256) | Bl(256:512)], n=1023 zeros
__global__ __launch_bounds__(256) void conv_gwt(const float* __restrict__ gw) {
    int idx = blockIdx.x * 256 + threadIdx.x;         // k*1024 + n, coalesced read
    int k = idx >> 10, n = idx & 1023;
    float v = (n < GATES) ? gw[(size_t)k * GATES + n] : 0.f;
    __nv_bfloat16 h, l;
    split2(v, h, l);
    __nv_bfloat16* r = &g_gws[(size_t)n * 512];
    r[k] = h; r[256 + k] = l;
}
// z [128,1024] -> g_zs rows [Bh(0:1024) | Bl(1024:2048)]
__global__ __launch_bounds__(256) void conv_z(const float* __restrict__ z) {
    int i = blockIdx.x * 256 + threadIdx.x;           // float4 index
    int n = i >> 8, col = (i & 255) * 4;
    float4 v = reinterpret_cast<const float4*>(z)[i];
    __nv_bfloat16 h[4], l[4];
    split2(v.x, h[0], l[0]); split2(v.y, h[1], l[1]);
    split2(v.z, h[2], l[2]); split2(v.w, h[3], l[3]);
    __nv_bfloat16* r = &g_zs[(size_t)n * 2048 + col];
    *reinterpret_cast<__nv_bfloat162*>(r)        = __nv_bfloat162{h[0], h[1]};
    *reinterpret_cast<__nv_bfloat162*>(r + 2)    = __nv_bfloat162{h[2], h[3]};
    *reinterpret_cast<__nv_bfloat162*>(r + 1024) = __nv_bfloat162{l[0], l[1]};
    *reinterpret_cast<__nv_bfloat162*>(r + 1026) = __nv_bfloat162{l[2], l[3]};
}

// ---------------- bf16 HMMA GEMM: D = Ah@Bh^T + Ah@Bl^T + Al@Bh^T ----------
// CTA 128x128, 8 warps (2x4), warp tile 64x32.
// K-chunk 64, 3-stage cp.async ring (per-chunk commit groups).
// G2S: 2 threads per 128B row, 4x16B quads EACH (R10/R11 bug: only 2 quads
// were loaded -> K-elems 32..63 uninitialized -> NaN).
// Tail: at the last chunk the newest pending group IS that chunk -> CPWAIT(0).
// smem row stride 72 elems (144 B): 16B-aligned, conflict-free ldmatrix.
// Term walk: t=0: Ah,Bh  t=1: Ah,Bl  t=2: Al,Bh  (A/B stored [hi|lo], 2K cols).
template <int K, bool SIG>
__global__ __launch_bounds__(256, 2) void k_mma(const float* __restrict__ gb,
                                                float* __restrict__ outp) {
    extern __shared__ __align__(16) char smem[];
    constexpr int CPT = K / 64;                       // chunks per term
    constexpr int NCH = 3 * CPT;
    constexpr int KPA = 2 * K;                        // stored row length
    constexpr int SST = 72;                           // smem row stride (elems)
    constexpr int TILEB = 128 * SST * 2;              // 18432 B per operand tile
    constexpr int STG   = 2 * TILEB;                  // 36864 B per stage
    constexpr int STAGES = 3;

    const __nv_bfloat16* __restrict__ A = SIG ? g_xs  : g_ls;
    const __nv_bfloat16* __restrict__ B = SIG ? g_gws : g_zs;

    const int tid = threadIdx.x, wid = tid >> 5, lane = tid & 31;
    const int m0 = blockIdx.y * 128, n0 = blockIdx.x * 128;
    const int wm = (wid & 1) * 64, wn = (wid >> 1) * 32;
    const uint32_t sb = smem_u32(smem);

    const __nv_bfloat16* gA = A + (size_t)m0 * KPA;
    const __nv_bfloat16* gB = B + (size_t)n0 * KPA;

    float acc[4][4][4];
    #pragma unroll
    for (int i = 0; i < 4; i++)
        #pragma unroll
        for (int j = 0; j < 4; j++)
            #pragma unroll
            for (int k = 0; k < 4; k++) acc[i][j][k] = 0.f;

    // ldmatrix lane addressing
    const int arow  = wm + (lane & 15);
    const int ahalf = (lane >> 4) * 8;
    const int brow  = wn + (lane & 7) + ((lane >> 4) << 3);
    const int bkof  = ((lane >> 3) & 1) * 8;

    // G2S: 2 threads per row; each thread 4x16B quads per operand tile
    const int lrow = tid >> 1, lq0 = (tid & 1) * 4;

    auto load_chunk = [&](int c, int s) {
        const int t  = c / CPT;
        const int kc = c - t * CPT;
        const int a_off = ((t == 2) ? K : 0) + kc * 64;
        const int b_off = ((t == 1) ? K : 0) + kc * 64;
        const uint32_t base = sb + s * STG;
        const __nv_bfloat16* pa = gA + (size_t)lrow * KPA + a_off;
        const __nv_bfloat16* pb = gB + (size_t)lrow * KPA + b_off;
        #pragma unroll
        for (int i = 0; i < 4; i++) {
            uint32_t so = (uint32_t)(lrow * SST + (lq0 + i) * 8) * 2;
            CP16(base + so,         pa + (lq0 + i) * 8);
            CP16(base + TILEB + so, pb + (lq0 + i) * 8);
        }
        CPCOMMIT();
    };

    load_chunk(0, 0);
    load_chunk(1, 1);
    for (int c = 0; c < NCH; c++) {
        const int s = c % STAGES;
        if (c == NCH - 1) { CPWAIT(0); }              // last chunk: drain ALL
        else              { CPWAIT(1); }              // steady: 1 newer pending
        __syncthreads();
        if (c + STAGES - 1 < NCH)                     // refill freed stage
            load_chunk(c + STAGES - 1, (c + STAGES - 1) % STAGES);

        const uint32_t aB = sb + s * STG;
        const uint32_t bB = aB + TILEB;
        #pragma unroll
        for (int kk = 0; kk < 4; kk++) {
            uint32_t a[4][4], b[2][4];
            #pragma unroll
            for (int mt = 0; mt < 4; mt++)
                ldm4(a[mt], aB + (uint32_t)((arow + mt * 16) * SST + kk * 16 + ahalf) * 2);
            #pragma unroll
            for (int np = 0; np < 2; np++)
                ldm4(b[np], bB + (uint32_t)((brow + np * 16) * SST + kk * 16 + bkof) * 2);
            #pragma unroll
            for (int mt = 0; mt < 4; mt++)
                #pragma unroll
                for (int nt = 0; nt < 4; nt++)
                    mma16816(acc[mt][nt], a[mt], &b[nt >> 1][(nt & 1) * 2]);
        }
        __syncthreads();                              // protect stage reuse
    }

    // epilogue
    const int mg = m0 + wm + (lane >> 2);
    const int cg = (lane & 3) * 2;
    #pragma unroll
    for (int mt = 0; mt < 4; mt++) {
        const int m = mg + mt * 16;
        #pragma unroll
        for (int nt = 0; nt < 4; nt++) {
            const int n = n0 + wn + nt * 8 + cg;
            float* ac = acc[mt][nt];
            if (SIG) {
                float b0 = (n     < GATES) ? gb[n]     : 0.f;
                float b1 = (n + 1 < GATES) ? gb[n + 1] : 0.f;
                float2 v0{1.f / (1.f + __expf(-(ac[0] + b0))),
                          1.f / (1.f + __expf(-(ac[1] + b1)))};
                float2 v1{1.f / (1.f + __expf(-(ac[2] + b0))),
                          1.f / (1.f + __expf(-(ac[3] + b1)))};
                *reinterpret_cast<float2*>(&g_gat[(size_t)m * GPAD + n])       = v0;
                *reinterpret_cast<float2*>(&g_gat[(size_t)(m + 8) * GPAD + n]) = v1;
            } else {
                *reinterpret_cast<float2*>(&outp[(size_t)m * OUTF + n])       = float2{ac[0], ac[1]};
                *reinterpret_cast<float2*>(&outp[(size_t)(m + 8) * OUTF + n]) = float2{ac[2], ac[3]};
            }
        }
    }
}

// ---------------- K2: leaf densities + split [Ah|Al] ------------------------
__global__ __launch_bounds__(256) void k_leaf() {
    __shared__ __align__(16) float bufA[8][512];
    __shared__ __align__(16) float bufB[8][1024];
    const int w    = threadIdx.x >> 5;
    const int lane = threadIdx.x & 31;
    const int row  = blockIdx.x * 8 + w;
    const float* __restrict__ gr = &g_gat[(size_t)row * GPAD];

    if (lane == 0) bufB[w][0] = 1.f;
    __syncwarp();

    for (int d = 0; d < 10; d++) {
        const int n = 1 << d, start = n - 1;
        float* src = (d & 1) ? bufA[w] : bufB[w];
        float* dst = (d & 1) ? bufB[w] : bufA[w];
        for (int i = lane; i < n; i += 32) {
            float p = src[i], g = gr[start + i];
            dst[2 * i]     = p * g;
            dst[2 * i + 1] = p * (1.f - g);
        }
        __syncwarp();
    }

    const size_t base = (size_t)row * 2048;
    #pragma unroll
    for (int j = 0; j < 8; j++) {
        int i = (j * 32 + lane) * 4;
        float4 v = *reinterpret_cast<float4*>(&bufB[w][i]);
        __nv_bfloat16 h[4], l[4];
        split2(v.x, h[0], l[0]); split2(v.y, h[1], l[1]);
        split2(v.z, h[2], l[2]); split2(v.w, h[3], l[3]);
        __nv_bfloat16* r = &g_ls[base + i];
        *reinterpret_cast<__nv_bfloat162*>(r)        = __nv_bfloat162{h[0], h[1]};
        *reinterpret_cast<__nv_bfloat162*>(r + 2)    = __nv_bfloat162{h[2], h[3]};
        *reinterpret_cast<__nv_bfloat162*>(r + 1024) = __nv_bfloat162{l[0], l[1]};
        *reinterpret_cast<__nv_bfloat162*>(r + 1026) = __nv_bfloat162{l[2], l[3]};
    }
}

// ---------------------------------------------------------------------------
extern "C" void kernel_launch(void* const* d_in, const int* in_sizes, int n_in,
                              void* d_out, int out_size) {
    const float* x  = (const float*)d_in[0];   // [16384, 256]
    const float* gw = (const float*)d_in[1];   // [256, 1023]
    const float* gb = (const float*)d_in[2];   // [1023]
    const float* z  = (const float*)d_in[3];   // [128, 1024]
    float* out = (float*)d_out;                // [16384, 128]

    const int SMEM_SZ = 3 * 36864;             // 110592 B (3 stages)
    cudaFuncSetAttribute(k_mma<INF, true>,     cudaFuncAttributeMaxDynamicSharedMemorySize, SMEM_SZ);
    cudaFuncSetAttribute(k_mma<LEAVES, false>, cudaFuncAttributeMaxDynamicSharedMemorySize, SMEM_SZ);

    conv_x  <<<(BATCH * INF / 4) / 256, 256>>>(x);
    conv_gwt<<<(INF * GPAD) / 256, 256>>>(gw);
    conv_z  <<<(OUTF * LEAVES / 4) / 256, 256>>>(z);

    k_mma<INF, true><<<dim3(GPAD / 128, BATCH / 128), 256, SMEM_SZ>>>(gb, out);   // -> g_gat
    k_leaf<<<BATCH / 8, 256>>>();                                                 // -> g_ls
    k_mma<LEAVES, false><<<dim3(1, BATCH / 128), 256, SMEM_SZ>>>(gb, out);        // -> out
}

// round 13
// speedup vs baseline: 1.1530x; 1.1530x over previous
#include <cuda_runtime.h>
#include <cuda_bf16.h>
#include <cstdint>

#define BATCH   16384
#define INF     256
#define GATES   1023
#define GPAD    1024
#define OUTF    128
#define LEAVES  1024

// ---------------- device scratch (static, no runtime allocation) ----------
// A-side layouts: [Ah | Al] (2K cols). B-side: [Bh | Bl] (2K cols).
__device__ __nv_bfloat16 g_xs[BATCH * 2 * INF];           // x'   [16384][512]
__device__ __nv_bfloat16 g_gws[GPAD * 2 * INF];           // gw'^T[1024][512] (row 1023 = 0)
__device__ __nv_bfloat16 g_zs[OUTF * 2 * LEAVES];         // z'   [128][2048]
__device__ __nv_bfloat16 g_ls[(size_t)BATCH * 2 * LEAVES];// leaf'[16384][2048]
__device__ float         g_gat[BATCH * GPAD];             // sigmoid gatings (fp32)
__device__ float         g_part[2 * BATCH * OUTF];        // split-K partials (16MB)

// ---------------- PTX helpers (sm_80-class, compile on compute_103) --------
__device__ __forceinline__ uint32_t smem_u32(const void* p) {
    uint32_t a;
    asm("{ .reg .u64 t; cvta.to.shared.u64 t, %1; cvt.u32.u64 %0, t; }"
        : "=r"(a) : "l"(p));
    return a;
}
#define CP16(dst, src) \
    asm volatile("cp.async.cg.shared.global [%0], [%1], 16;" \
                 :: "r"(dst), "l"(src) : "memory")
#define CPCOMMIT() asm volatile("cp.async.commit_group;" ::: "memory")
#define CPWAIT(n)  asm volatile("cp.async.wait_group %0;" :: "n"(n) : "memory")

__device__ __forceinline__ void ldm4(uint32_t* r, uint32_t addr) {
    asm volatile("ldmatrix.sync.aligned.m8n8.x4.shared.b16 {%0,%1,%2,%3}, [%4];"
                 : "=r"(r[0]), "=r"(r[1]), "=r"(r[2]), "=r"(r[3]) : "r"(addr));
}
__device__ __forceinline__ void mma16816(float* d, const uint32_t* a, const uint32_t* b) {
    asm volatile("mma.sync.aligned.m16n8k16.row.col.f32.bf16.bf16.f32 "
                 "{%0,%1,%2,%3}, {%4,%5,%6,%7}, {%8,%9}, {%0,%1,%2,%3};"
                 : "+f"(d[0]), "+f"(d[1]), "+f"(d[2]), "+f"(d[3])
                 : "r"(a[0]), "r"(a[1]), "r"(a[2]), "r"(a[3]),
                   "r"(b[0]), "r"(b[1]));
}
__device__ __forceinline__ void split2(float v, __nv_bfloat16& h, __nv_bfloat16& l) {
    h = __float2bfloat16(v);
    l = __float2bfloat16(v - __bfloat162float(h));
}

// ---------------- conversion kernels --------------------------------------
__global__ __launch_bounds__(256) void conv_x(const float* __restrict__ x) {
    int i = blockIdx.x * 256 + threadIdx.x;           // float4 index
    int row = i >> 6, col = (i & 63) * 4;
    float4 v = reinterpret_cast<const float4*>(x)[i];
    __nv_bfloat16 h[4], l[4];
    split2(v.x, h[0], l[0]); split2(v.y, h[1], l[1]);
    split2(v.z, h[2], l[2]); split2(v.w, h[3], l[3]);
    __nv_bfloat16* r = &g_xs[(size_t)row * 512 + col];
    *reinterpret_cast<__nv_bfloat162*>(r)       = __nv_bfloat162{h[0], h[1]};
    *reinterpret_cast<__nv_bfloat162*>(r + 2)   = __nv_bfloat162{h[2], h[3]};
    *reinterpret_cast<__nv_bfloat162*>(r + 256) = __nv_bfloat162{l[0], l[1]};
    *reinterpret_cast<__nv_bfloat162*>(r + 258) = __nv_bfloat162{l[2], l[3]};
}
__global__ __launch_bounds__(256) void conv_gwt(const float* __restrict__ gw) {
    int idx = blockIdx.x * 256 + threadIdx.x;         // k*1024 + n, coalesced read
    int k = idx >> 10, n = idx & 1023;
    float v = (n < GATES) ? gw[(size_t)k * GATES + n] : 0.f;
    __nv_bfloat16 h, l;
    split2(v, h, l);
    __nv_bfloat16* r = &g_gws[(size_t)n * 512];
    r[k] = h; r[256 + k] = l;
}
__global__ __launch_bounds__(256) void conv_z(const float* __restrict__ z) {
    int i = blockIdx.x * 256 + threadIdx.x;           // float4 index
    int n = i >> 8, col = (i & 255) * 4;
    float4 v = reinterpret_cast<const float4*>(z)[i];
    __nv_bfloat16 h[4], l[4];
    split2(v.x, h[0], l[0]); split2(v.y, h[1], l[1]);
    split2(v.z, h[2], l[2]); split2(v.w, h[3], l[3]);
    __nv_bfloat16* r = &g_zs[(size_t)n * 2048 + col];
    *reinterpret_cast<__nv_bfloat162*>(r)        = __nv_bfloat162{h[0], h[1]};
    *reinterpret_cast<__nv_bfloat162*>(r + 2)    = __nv_bfloat162{h[2], h[3]};
    *reinterpret_cast<__nv_bfloat162*>(r + 1024) = __nv_bfloat162{l[0], l[1]};
    *reinterpret_cast<__nv_bfloat162*>(r + 1026) = __nv_bfloat162{l[2], l[3]};
}

// ---------------- bf16 HMMA GEMM: D = Ah@Bh^T + Ah@Bl^T + Al@Bh^T ----------
// CTA 128x128, 8 warps (2x4), warp tile 64x32.
// K-chunk 64, 3-stage cp.async ring (per-chunk commit groups).
// G2S: 4 threads/row; per warp instruction = 8 rows x 64B CONTIGUOUS
//      (R12's interleaved 2-thread/row pattern scattered sectors -> L2 45%).
// Tail: at the last local chunk the newest pending group IS it -> CPWAIT(0).
// SPLITK: gridDim.z CTAs split the chunk list; partials land in g_part.
// smem row stride 72 elems (144 B): 16B-aligned, conflict-free ldmatrix.
// Term walk: t=0: Ah,Bh  t=1: Ah,Bl  t=2: Al,Bh  (A/B stored [hi|lo], 2K cols).
template <int K, bool SIG, int SPLITK>
__global__ __launch_bounds__(256, 2) void k_mma(const float* __restrict__ gb,
                                                float* __restrict__ outp) {
    extern __shared__ __align__(16) char smem[];
    constexpr int CPT = K / 64;                       // chunks per term
    constexpr int NCH = 3 * CPT;
    constexpr int LCH = NCH / SPLITK;                 // chunks this CTA
    constexpr int KPA = 2 * K;                        // stored row length
    constexpr int SST = 72;                           // smem row stride (elems)
    constexpr int TILEB = 128 * SST * 2;              // 18432 B per operand tile
    constexpr int STG   = 2 * TILEB;                  // 36864 B per stage
    constexpr int STAGES = 3;

    const __nv_bfloat16* __restrict__ A = SIG ? g_xs  : g_ls;
    const __nv_bfloat16* __restrict__ B = SIG ? g_gws : g_zs;

    const int tid = threadIdx.x, wid = tid >> 5, lane = tid & 31;
    const int m0 = blockIdx.y * 128, n0 = blockIdx.x * 128;
    const int zc = blockIdx.z;
    const int c0 = zc * LCH;
    const int wm = (wid & 1) * 64, wn = (wid >> 1) * 32;
    const uint32_t sb = smem_u32(smem);

    const __nv_bfloat16* gA = A + (size_t)m0 * KPA;
    const __nv_bfloat16* gB = B + (size_t)n0 * KPA;

    float acc[4][4][4];
    #pragma unroll
    for (int i = 0; i < 4; i++)
        #pragma unroll
        for (int j = 0; j < 4; j++)
            #pragma unroll
            for (int k = 0; k < 4; k++) acc[i][j][k] = 0.f;

    // ldmatrix lane addressing
    const int arow  = wm + (lane & 15);
    const int ahalf = (lane >> 4) * 8;
    const int brow  = wn + (lane & 7) + ((lane >> 4) << 3);
    const int bkof  = ((lane >> 3) & 1) * 8;

    // G2S: 4 threads/row (64 rows/pass, 2 passes); quad = (tid&3) + 4*i
    const int lrow = tid >> 2, lq = tid & 3;

    auto load_chunk = [&](int c, int s) {
        const int t  = c / CPT;
        const int kc = c - t * CPT;
        const int a_off = ((t == 2) ? K : 0) + kc * 64;
        const int b_off = ((t == 1) ? K : 0) + kc * 64;
        const uint32_t base = sb + s * STG;
        #pragma unroll
        for (int rg = 0; rg < 2; rg++) {
            const int row = lrow + rg * 64;
            const __nv_bfloat16* pa = gA + (size_t)row * KPA + a_off;
            const __nv_bfloat16* pb = gB + (size_t)row * KPA + b_off;
            #pragma unroll
            for (int i = 0; i < 2; i++) {
                const int q = lq + 4 * i;
                uint32_t so = (uint32_t)(row * SST + q * 8) * 2;
                CP16(base + so,         pa + q * 8);
                CP16(base + TILEB + so, pb + q * 8);
            }
        }
        CPCOMMIT();
    };

    load_chunk(c0, 0);
    load_chunk(c0 + 1, 1);
    for (int lc = 0; lc < LCH; lc++) {
        const int s = lc % STAGES;
        if (lc == LCH - 1) { CPWAIT(0); }             // last chunk: drain ALL
        else               { CPWAIT(1); }             // steady: 1 newer pending
        __syncthreads();
        if (lc + STAGES - 1 < LCH)                    // refill freed stage
            load_chunk(c0 + lc + STAGES - 1, (lc + STAGES - 1) % STAGES);

        const uint32_t aB = sb + s * STG;
        const uint32_t bB = aB + TILEB;
        #pragma unroll
        for (int kk = 0; kk < 4; kk++) {
            uint32_t a[4][4], b[2][4];
            #pragma unroll
            for (int mt = 0; mt < 4; mt++)
                ldm4(a[mt], aB + (uint32_t)((arow + mt * 16) * SST + kk * 16 + ahalf) * 2);
            #pragma unroll
            for (int np = 0; np < 2; np++)
                ldm4(b[np], bB + (uint32_t)((brow + np * 16) * SST + kk * 16 + bkof) * 2);
            #pragma unroll
            for (int mt = 0; mt < 4; mt++)
                #pragma unroll
                for (int nt = 0; nt < 4; nt++)
                    mma16816(acc[mt][nt], a[mt], &b[nt >> 1][(nt & 1) * 2]);
        }
        __syncthreads();                              // protect stage reuse
    }

    // epilogue
    const int mg = m0 + wm + (lane >> 2);
    const int cg = (lane & 3) * 2;
    #pragma unroll
    for (int mt = 0; mt < 4; mt++) {
        const int m = mg + mt * 16;
        #pragma unroll
        for (int nt = 0; nt < 4; nt++) {
            const int n = n0 + wn + nt * 8 + cg;
            float* ac = acc[mt][nt];
            if (SIG) {
                float b0 = (n     < GATES) ? gb[n]     : 0.f;
                float b1 = (n + 1 < GATES) ? gb[n + 1] : 0.f;
                float2 v0{1.f / (1.f + __expf(-(ac[0] + b0))),
                          1.f / (1.f + __expf(-(ac[1] + b1)))};
                float2 v1{1.f / (1.f + __expf(-(ac[2] + b0))),
                          1.f / (1.f + __expf(-(ac[3] + b1)))};
                *reinterpret_cast<float2*>(&g_gat[(size_t)m * GPAD + n])       = v0;
                *reinterpret_cast<float2*>(&g_gat[(size_t)(m + 8) * GPAD + n]) = v1;
            } else if (SPLITK > 1) {
                float* pp = &g_part[(size_t)zc * BATCH * OUTF];
                *reinterpret_cast<float2*>(&pp[(size_t)m * OUTF + n])       = float2{ac[0], ac[1]};
                *reinterpret_cast<float2*>(&pp[(size_t)(m + 8) * OUTF + n]) = float2{ac[2], ac[3]};
            } else {
                *reinterpret_cast<float2*>(&outp[(size_t)m * OUTF + n])       = float2{ac[0], ac[1]};
                *reinterpret_cast<float2*>(&outp[(size_t)(m + 8) * OUTF + n]) = float2{ac[2], ac[3]};
            }
        }
    }
}

// ---------------- split-K reduce: out = part0 + part1 ----------------------
__global__ __launch_bounds__(256) void k_red(float* __restrict__ out) {
    int i = blockIdx.x * 256 + threadIdx.x;           // float4 index
    const float4* p0 = reinterpret_cast<const float4*>(g_part);
    const float4* p1 = reinterpret_cast<const float4*>(g_part + (size_t)BATCH * OUTF);
    float4 a = p0[i], b = p1[i];
    reinterpret_cast<float4*>(out)[i] =
        make_float4(a.x + b.x, a.y + b.y, a.z + b.z, a.w + b.w);
}

// ---------------- K2: leaf densities + split [Ah|Al] ------------------------
__global__ __launch_bounds__(256) void k_leaf() {
    __shared__ __align__(16) float bufA[8][512];
    __shared__ __align__(16) float bufB[8][1024];
    const int w    = threadIdx.x >> 5;
    const int lane = threadIdx.x & 31;
    const int row  = blockIdx.x * 8 + w;
    const float* __restrict__ gr = &g_gat[(size_t)row * GPAD];

    if (lane == 0) bufB[w][0] = 1.f;
    __syncwarp();

    for (int d = 0; d < 10; d++) {
        const int n = 1 << d, start = n - 1;
        float* src = (d & 1) ? bufA[w] : bufB[w];
        float* dst = (d & 1) ? bufB[w] : bufA[w];
        for (int i = lane; i < n; i += 32) {
            float p = src[i], g = gr[start + i];
            dst[2 * i]     = p * g;
            dst[2 * i + 1] = p * (1.f - g);
        }
        __syncwarp();
    }

    const size_t base = (size_t)row * 2048;
    #pragma unroll
    for (int j = 0; j < 8; j++) {
        int i = (j * 32 + lane) * 4;
        float4 v = *reinterpret_cast<float4*>(&bufB[w][i]);
        __nv_bfloat16 h[4], l[4];
        split2(v.x, h[0], l[0]); split2(v.y, h[1], l[1]);
        split2(v.z, h[2], l[2]); split2(v.w, h[3], l[3]);
        __nv_bfloat16* r = &g_ls[base + i];
        *reinterpret_cast<__nv_bfloat162*>(r)        = __nv_bfloat162{h[0], h[1]};
        *reinterpret_cast<__nv_bfloat162*>(r + 2)    = __nv_bfloat162{h[2], h[3]};
        *reinterpret_cast<__nv_bfloat162*>(r + 1024) = __nv_bfloat162{l[0], l[1]};
        *reinterpret_cast<__nv_bfloat162*>(r + 1026) = __nv_bfloat162{l[2], l[3]};
    }
}

// ---------------------------------------------------------------------------
extern "C" void kernel_launch(void* const* d_in, const int* in_sizes, int n_in,
                              void* d_out, int out_size) {
    const float* x  = (const float*)d_in[0];   // [16384, 256]
    const float* gw = (const float*)d_in[1];   // [256, 1023]
    const float* gb = (const float*)d_in[2];   // [1023]
    const float* z  = (const float*)d_in[3];   // [128, 1024]
    float* out = (float*)d_out;                // [16384, 128]

    const int SMEM_SZ = 3 * 36864;             // 110592 B (3 stages)
    cudaFuncSetAttribute((const void*)k_mma<INF, true, 1>,
                         cudaFuncAttributeMaxDynamicSharedMemorySize, SMEM_SZ);
    cudaFuncSetAttribute((const void*)k_mma<LEAVES, false, 2>,
                         cudaFuncAttributeMaxDynamicSharedMemorySize, SMEM_SZ);

    conv_x  <<<(BATCH * INF / 4) / 256, 256>>>(x);
    conv_gwt<<<(INF * GPAD) / 256, 256>>>(gw);
    conv_z  <<<(OUTF * LEAVES / 4) / 256, 256>>>(z);

    k_mma<INF, true, 1><<<dim3(GPAD / 128, BATCH / 128, 1), 256, SMEM_SZ>>>(gb, out);
    k_leaf<<<BATCH / 8, 256>>>();
    k_mma<LEAVES, false, 2><<<dim3(1, BATCH / 128, 2), 256, SMEM_SZ>>>(gb, out);
    k_red<<<(BATCH * OUTF / 4) / 256, 256>>>(out);
}

// round 16
// speedup vs baseline: 1.5899x; 1.3790x over previous
#include <cuda_runtime.h>
#include <cuda_fp16.h>
#include <cstdint>

#define BATCH   16384
#define INF     256
#define GATES   1023
#define GPAD    1024
#define OUTF    128
#define LEAVES  1024

// ---------------- device scratch (static, no runtime allocation) ----------
// Large matrices: SINGLE fp16. Small matrices: [Bh | Bl] fp16 pair (2K cols).
__device__ __half g_x1[BATCH * INF];                     // fp16(x)      [16384][256]
__device__ __half g_gw2[GPAD * 2 * INF];                 // gw'^T hi|lo  [1024][512] (row 1023 = 0)
__device__ __half g_z2[OUTF * 2 * LEAVES];               // z hi|lo      [128][2048]
__device__ __half g_l1[(size_t)BATCH * LEAVES];          // fp16(leaf)   [16384][1024]
__device__ float  g_gat[BATCH * GPAD];                   // sigmoid gatings (fp32)
__device__ float  g_part[2 * BATCH * OUTF];              // split-K partials

// ---------------- PTX helpers (sm_80-class, compile on compute_103) --------
__device__ __forceinline__ uint32_t smem_u32(const void* p) {
    uint32_t a;
    asm("{ .reg .u64 t; cvta.to.shared.u64 t, %1; cvt.u32.u64 %0, t; }"
        : "=r"(a) : "l"(p));
    return a;
}
#define CP16(dst, src) \
    asm volatile("cp.async.cg.shared.global [%0], [%1], 16;" \
                 :: "r"(dst), "l"(src) : "memory")
#define CPCOMMIT() asm volatile("cp.async.commit_group;" ::: "memory")
#define CPWAIT(n)  asm volatile("cp.async.wait_group %0;" :: "n"(n) : "memory")

__device__ __forceinline__ void ldm4(uint32_t* r, uint32_t addr) {
    asm volatile("ldmatrix.sync.aligned.m8n8.x4.shared.b16 {%0,%1,%2,%3}, [%4];"
                 : "=r"(r[0]), "=r"(r[1]), "=r"(r[2]), "=r"(r[3]) : "r"(addr));
}
__device__ __forceinline__ void mma16816(float* d, const uint32_t* a, const uint32_t* b) {
    asm volatile("mma.sync.aligned.m16n8k16.row.col.f32.f16.f16.f32 "
                 "{%0,%1,%2,%3}, {%4,%5,%6,%7}, {%8,%9}, {%0,%1,%2,%3};"
                 : "+f"(d[0]), "+f"(d[1]), "+f"(d[2]), "+f"(d[3])
                 : "r"(a[0]), "r"(a[1]), "r"(a[2]), "r"(a[3]),
                   "r"(b[0]), "r"(b[1]));
}
__device__ __forceinline__ void hsplit(float v, __half& h, __half& l) {
    h = __float2half_rn(v);
    l = __float2half_rn(v - __half2float(h));
}

// ---------------- conversion kernels --------------------------------------
// x -> single fp16 (error absorbed by the 2-term scheme on the B side)
__global__ __launch_bounds__(256) void conv_x(const float* __restrict__ x) {
    int i = blockIdx.x * 256 + threadIdx.x;           // float4 index
    float4 v = reinterpret_cast<const float4*>(x)[i];
    __half2 a{__float2half_rn(v.x), __float2half_rn(v.y)};
    __half2 b{__float2half_rn(v.z), __float2half_rn(v.w)};
    *reinterpret_cast<__half2*>(&g_x1[i * 4])     = a;
    *reinterpret_cast<__half2*>(&g_x1[i * 4 + 2]) = b;
}
// gw [256,1023] -> gw'^T rows n: [Bh(0:256) | Bl(256:512)], n=1023 zeros
__global__ __launch_bounds__(256) void conv_gwt(const float* __restrict__ gw) {
    int idx = blockIdx.x * 256 + threadIdx.x;         // k*1024 + n, coalesced read
    int k = idx >> 10, n = idx & 1023;
    float v = (n < GATES) ? gw[(size_t)k * GATES + n] : 0.f;
    __half h, l;
    hsplit(v, h, l);
    __half* r = &g_gw2[(size_t)n * 512];
    r[k] = h; r[256 + k] = l;
}
// z [128,1024] -> rows [zh(0:1024) | zl(1024:2048)]
__global__ __launch_bounds__(256) void conv_z(const float* __restrict__ z) {
    int i = blockIdx.x * 256 + threadIdx.x;           // float4 index
    int n = i >> 8, col = (i & 255) * 4;
    float4 v = reinterpret_cast<const float4*>(z)[i];
    __half h[4], l[4];
    hsplit(v.x, h[0], l[0]); hsplit(v.y, h[1], l[1]);
    hsplit(v.z, h[2], l[2]); hsplit(v.w, h[3], l[3]);
    __half* r = &g_z2[(size_t)n * 2048 + col];
    *reinterpret_cast<__half2*>(r)        = __half2{h[0], h[1]};
    *reinterpret_cast<__half2*>(r + 2)    = __half2{h[2], h[3]};
    *reinterpret_cast<__half2*>(r + 1024) = __half2{l[0], l[1]};
    *reinterpret_cast<__half2*>(r + 1026) = __half2{l[2], l[3]};
}

// ---------------- fp16 HMMA GEMM: D = A@Bh^T + A@Bl^T ----------------------
// CTA 128x128, 8 warps (2x4), warp tile 64x32.
// Chunk = K-64 slab holding THREE tiles {A, Bh, Bl}; A loaded once, both
// B terms accumulated per kk. 2-stage cp.async ring, per-chunk commit groups.
// G2S: 4 threads/row; warp instruction = 8 rows x 64B contiguous.
// smem row stride 72 elems (144 B): 16B-aligned, conflict-free ldmatrix.
// SPLITK: gridDim.z CTAs split the chunk list; partials land in g_part.
template <int K, bool SIG, int SPLITK>
__global__ __launch_bounds__(256, 2) void k_mma(const float* __restrict__ gb,
                                                float* __restrict__ outp) {
    extern __shared__ __align__(16) char smem[];
    constexpr int NCH = K / 64;                       // chunks (kc only)
    constexpr int LCH = NCH / SPLITK;                 // chunks this CTA
    constexpr int KPB = 2 * K;                        // B stored row length
    constexpr int SST = 72;                           // smem row stride (elems)
    constexpr int TILEB = 128 * SST * 2;              // 18432 B per tile
    constexpr int STG   = 3 * TILEB;                  // 55296 B per stage {A,Bh,Bl}
    constexpr int STAGES = 2;

    const __half* __restrict__ A = SIG ? g_x1  : g_l1;
    const __half* __restrict__ B = SIG ? g_gw2 : g_z2;

    const int tid = threadIdx.x, wid = tid >> 5, lane = tid & 31;
    const int m0 = blockIdx.y * 128, n0 = blockIdx.x * 128;
    const int zc = blockIdx.z;
    const int c0 = zc * LCH;
    const int wm = (wid & 1) * 64, wn = (wid >> 1) * 32;
    const uint32_t sb = smem_u32(smem);

    const __half* gA = A + (size_t)m0 * K;
    const __half* gB = B + (size_t)n0 * KPB;

    float acc[4][4][4];
    #pragma unroll
    for (int i = 0; i < 4; i++)
        #pragma unroll
        for (int j = 0; j < 4; j++)
            #pragma unroll
            for (int k = 0; k < 4; k++) acc[i][j][k] = 0.f;

    // ldmatrix lane addressing
    const int arow  = wm + (lane & 15);
    const int ahalf = (lane >> 4) * 8;
    const int brow  = wn + (lane & 7) + ((lane >> 4) << 3);
    const int bkof  = ((lane >> 3) & 1) * 8;

    // G2S: 4 threads/row (64 rows/pass, 2 passes); quad = (tid&3) + 4*i
    const int lrow = tid >> 2, lq = tid & 3;

    auto load_chunk = [&](int c, int s) {
        const int a_off = c * 64;
        const uint32_t base = sb + s * STG;
        #pragma unroll
        for (int rg = 0; rg < 2; rg++) {
            const int row = lrow + rg * 64;
            const __half* pa = gA + (size_t)row * K   + a_off;
            const __half* pb = gB + (size_t)row * KPB + a_off;   // Bh at c*64
            #pragma unroll
            for (int i = 0; i < 2; i++) {
                const int q = lq + 4 * i;
                uint32_t so = (uint32_t)(row * SST + q * 8) * 2;
                CP16(base + so,             pa + q * 8);             // A
                CP16(base + TILEB + so,     pb + q * 8);             // Bh
                CP16(base + 2 * TILEB + so, pb + K + q * 8);         // Bl
            }
        }
        CPCOMMIT();
    };

    load_chunk(c0, 0);
    if (LCH > 1) load_chunk(c0 + 1, 1);
    for (int lc = 0; lc < LCH; lc++) {
        const int s = lc & 1;
        if (lc == LCH - 1) { CPWAIT(0); }             // last chunk: drain ALL
        else               { CPWAIT(1); }             // steady: next still pending
        __syncthreads();

        const uint32_t aB  = sb + s * STG;
        const uint32_t bhB = aB + TILEB;
        const uint32_t blB = aB + 2 * TILEB;
        #pragma unroll
        for (int kk = 0; kk < 4; kk++) {
            uint32_t a[4][4], b[2][4];
            #pragma unroll
            for (int mt = 0; mt < 4; mt++)
                ldm4(a[mt], aB + (uint32_t)((arow + mt * 16) * SST + kk * 16 + ahalf) * 2);
            // term 0: Bh
            #pragma unroll
            for (int np = 0; np < 2; np++)
                ldm4(b[np], bhB + (uint32_t)((brow + np * 16) * SST + kk * 16 + bkof) * 2);
            #pragma unroll
            for (int mt = 0; mt < 4; mt++)
                #pragma unroll
                for (int nt = 0; nt < 4; nt++)
                    mma16816(acc[mt][nt], a[mt], &b[nt >> 1][(nt & 1) * 2]);
            // term 1: Bl (A frags reused)
            #pragma unroll
            for (int np = 0; np < 2; np++)
                ldm4(b[np], blB + (uint32_t)((brow + np * 16) * SST + kk * 16 + bkof) * 2);
            #pragma unroll
            for (int mt = 0; mt < 4; mt++)
                #pragma unroll
                for (int nt = 0; nt < 4; nt++)
                    mma16816(acc[mt][nt], a[mt], &b[nt >> 1][(nt & 1) * 2]);
        }
        __syncthreads();                              // stage reuse guard
        if (lc + STAGES < LCH)                        // refill freed stage
            load_chunk(c0 + lc + STAGES, s);
    }

    // epilogue
    const int mg = m0 + wm + (lane >> 2);
    const int cg = (lane & 3) * 2;
    #pragma unroll
    for (int mt = 0; mt < 4; mt++) {
        const int m = mg + mt * 16;
        #pragma unroll
        for (int nt = 0; nt < 4; nt++) {
            const int n = n0 + wn + nt * 8 + cg;
            float* ac = acc[mt][nt];
            if (SIG) {
                float b0 = (n     < GATES) ? gb[n]     : 0.f;
                float b1 = (n + 1 < GATES) ? gb[n + 1] : 0.f;
                float2 v0{1.f / (1.f + __expf(-(ac[0] + b0))),
                          1.f / (1.f + __expf(-(ac[1] + b1)))};
                float2 v1{1.f / (1.f + __expf(-(ac[2] + b0))),
                          1.f / (1.f + __expf(-(ac[3] + b1)))};
                *reinterpret_cast<float2*>(&g_gat[(size_t)m * GPAD + n])       = v0;
                *reinterpret_cast<float2*>(&g_gat[(size_t)(m + 8) * GPAD + n]) = v1;
            } else if (SPLITK > 1) {
                float* pp = &g_part[(size_t)zc * BATCH * OUTF];
                *reinterpret_cast<float2*>(&pp[(size_t)m * OUTF + n])       = float2{ac[0], ac[1]};
                *reinterpret_cast<float2*>(&pp[(size_t)(m + 8) * OUTF + n]) = float2{ac[2], ac[3]};
            } else {
                *reinterpret_cast<float2*>(&outp[(size_t)m * OUTF + n])       = float2{ac[0], ac[1]};
                *reinterpret_cast<float2*>(&outp[(size_t)(m + 8) * OUTF + n]) = float2{ac[2], ac[3]};
            }
        }
    }
}

// ---------------- split-K reduce: out = part0 + part1 ----------------------
__global__ __launch_bounds__(256) void k_red(float* __restrict__ out) {
    int i = blockIdx.x * 256 + threadIdx.x;           // float4 index
    const float4* p0 = reinterpret_cast<const float4*>(g_part);
    const float4* p1 = reinterpret_cast<const float4*>(g_part + (size_t)BATCH * OUTF);
    float4 a = p0[i], b = p1[i];
    reinterpret_cast<float4*>(out)[i] =
        make_float4(a.x + b.x, a.y + b.y, a.z + b.z, a.w + b.w);
}

// ---------------- K2: leaf densities -> single fp16 -------------------------
__global__ __launch_bounds__(256) void k_leaf() {
    __shared__ __align__(16) float bufA[8][512];
    __shared__ __align__(16) float bufB[8][1024];
    const int w    = threadIdx.x >> 5;
    const int lane = threadIdx.x & 31;
    const int row  = blockIdx.x * 8 + w;
    const float* __restrict__ gr = &g_gat[(size_t)row * GPAD];

    if (lane == 0) bufB[w][0] = 1.f;
    __syncwarp();

    for (int d = 0; d < 10; d++) {
        const int n = 1 << d, start = n - 1;
        float* src = (d & 1) ? bufA[w] : bufB[w];
        float* dst = (d & 1) ? bufB[w] : bufA[w];
        for (int i = lane; i < n; i += 32) {
            float p = src[i], g = gr[start + i];
            dst[2 * i]     = p * g;
            dst[2 * i + 1] = p * (1.f - g);
        }
        __syncwarp();
    }

    const size_t base = (size_t)row * LEAVES;
    #pragma unroll
    for (int j = 0; j < 8; j++) {
        int i = (j * 32 + lane) * 4;
        float4 v = *reinterpret_cast<float4*>(&bufB[w][i]);
        __half2 a{__float2half_rn(v.x), __float2half_rn(v.y)};
        __half2 b{__float2half_rn(v.z), __float2half_rn(v.w)};
        *reinterpret_cast<__half2*>(&g_l1[base + i])     = a;
        *reinterpret_cast<__half2*>(&g_l1[base + i + 2]) = b;
    }
}

// ---------------------------------------------------------------------------
extern "C" void kernel_launch(void* const* d_in, const int* in_sizes, int n_in,
                              void* d_out, int out_size) {
    const float* x  = (const float*)d_in[0];   // [16384, 256]
    const float* gw = (const float*)d_in[1];   // [256, 1023]
    const float* gb = (const float*)d_in[2];   // [1023]
    const float* z  = (const float*)d_in[3];   // [128, 1024]
    float* out = (float*)d_out;                // [16384, 128]

    const int SMEM_SZ = 2 * 3 * 18432;         // 110592 B (2 stages x {A,Bh,Bl})
    cudaFuncSetAttribute((const void*)k_mma<INF, true, 1>,
                         cudaFuncAttributeMaxDynamicSharedMemorySize, SMEM_SZ);
    cudaFuncSetAttribute((const void*)k_mma<LEAVES, false, 2>,
                         cudaFuncAttributeMaxDynamicSharedMemorySize, SMEM_SZ);

    conv_x  <<<(BATCH * INF / 4) / 256, 256>>>(x);
    conv_gwt<<<(INF * GPAD) / 256, 256>>>(gw);
    conv_z  <<<(OUTF * LEAVES / 4) / 256, 256>>>(z);

    k_mma<INF, true, 1><<<dim3(GPAD / 128, BATCH / 128, 1), 256, SMEM_SZ>>>(gb, out);
    k_leaf<<<BATCH / 8, 256>>>();
    k_mma<LEAVES, false, 2><<<dim3(1, BATCH / 128, 2), 256, SMEM_SZ>>>(gb, out);
    k_red<<<(BATCH * OUTF / 4) / 256, 256>>>(out);
}

// round 17
// speedup vs baseline: 1.8831x; 1.1844x over previous
#include <cuda_runtime.h>
#include <cuda_fp16.h>
#include <cstdint>

#define BATCH   16384
#define INF     256
#define GATES   1023
#define GPAD    1024
#define OUTF    128
#define LEAVES  1024
#define SPLK3   4

// ---------------- device scratch (static, no runtime allocation) ----------
__device__ __half g_x1[BATCH * INF];                     // fp16(x)    [16384][256]
__device__ __half g_gw1[GPAD * INF];                     // fp16(gw^T) [1024][256] (row 1023 = 0)
__device__ __half g_z1[OUTF * LEAVES];                   // fp16(z)    [128][1024]
__device__ __half g_l1[(size_t)BATCH * LEAVES];          // fp16(leaf) [16384][1024]
__device__ float  g_gat[BATCH * GPAD];                   // sigmoid gatings (fp32)
__device__ float  g_part[SPLK3 * BATCH * OUTF];          // split-K partials (32MB)

// ---------------- PTX helpers (sm_80-class, compile on compute_103) --------
__device__ __forceinline__ uint32_t smem_u32(const void* p) {
    uint32_t a;
    asm("{ .reg .u64 t; cvta.to.shared.u64 t, %1; cvt.u32.u64 %0, t; }"
        : "=r"(a) : "l"(p));
    return a;
}
#define CP16(dst, src) \
    asm volatile("cp.async.cg.shared.global [%0], [%1], 16;" \
                 :: "r"(dst), "l"(src) : "memory")
#define CPCOMMIT() asm volatile("cp.async.commit_group;" ::: "memory")
#define CPWAIT(n)  asm volatile("cp.async.wait_group %0;" :: "n"(n) : "memory")

__device__ __forceinline__ void ldm4(uint32_t* r, uint32_t addr) {
    asm volatile("ldmatrix.sync.aligned.m8n8.x4.shared.b16 {%0,%1,%2,%3}, [%4];"
                 : "=r"(r[0]), "=r"(r[1]), "=r"(r[2]), "=r"(r[3]) : "r"(addr));
}
__device__ __forceinline__ void mma16816(float* d, const uint32_t* a, const uint32_t* b) {
    asm volatile("mma.sync.aligned.m16n8k16.row.col.f32.f16.f16.f32 "
                 "{%0,%1,%2,%3}, {%4,%5,%6,%7}, {%8,%9}, {%0,%1,%2,%3};"
                 : "+f"(d[0]), "+f"(d[1]), "+f"(d[2]), "+f"(d[3])
                 : "r"(a[0]), "r"(a[1]), "r"(a[2]), "r"(a[3]),
                   "r"(b[0]), "r"(b[1]));
}

// ---------------- conversion kernels --------------------------------------
__global__ __launch_bounds__(256) void conv_x(const float* __restrict__ x) {
    int i = blockIdx.x * 256 + threadIdx.x;           // float4 index
    float4 v = reinterpret_cast<const float4*>(x)[i];
    *reinterpret_cast<__half2*>(&g_x1[i * 4])     = __half2{__float2half_rn(v.x), __float2half_rn(v.y)};
    *reinterpret_cast<__half2*>(&g_x1[i * 4 + 2]) = __half2{__float2half_rn(v.z), __float2half_rn(v.w)};
}
// gw [256,1023] -> fp16(gw^T) [1024][256], row 1023 zeros
__global__ __launch_bounds__(256) void conv_gwt(const float* __restrict__ gw) {
    int idx = blockIdx.x * 256 + threadIdx.x;         // k*1024 + n, coalesced read
    int k = idx >> 10, n = idx & 1023;
    float v = (n < GATES) ? gw[(size_t)k * GATES + n] : 0.f;
    g_gw1[(size_t)n * INF + k] = __float2half_rn(v);
}
__global__ __launch_bounds__(256) void conv_z(const float* __restrict__ z) {
    int i = blockIdx.x * 256 + threadIdx.x;           // float4 index
    float4 v = reinterpret_cast<const float4*>(z)[i];
    *reinterpret_cast<__half2*>(&g_z1[i * 4])     = __half2{__float2half_rn(v.x), __float2half_rn(v.y)};
    *reinterpret_cast<__half2*>(&g_z1[i * 4 + 2]) = __half2{__float2half_rn(v.z), __float2half_rn(v.w)};
}

// ---------------- fp16 HMMA GEMM: D = A @ B^T ------------------------------
// CTA 128x128, 8 warps (2x4), warp tile 64x32.
// K-chunk 64, 3-stage cp.async ring, per-chunk commit groups.
// G2S: 4 threads/row; warp instruction = 8 rows x 64B contiguous.
// Tail: at the last local chunk the newest pending group IS it -> CPWAIT(0).
// SPLITK: gridDim.z CTAs split the chunk list; partials land in g_part.
// smem row stride 72 elems (144 B): 16B-aligned, conflict-free ldmatrix.
template <int K, bool SIG, int SPLITK>
__global__ __launch_bounds__(256, 2) void k_mma(const float* __restrict__ gb,
                                                float* __restrict__ outp) {
    extern __shared__ __align__(16) char smem[];
    constexpr int NCH = K / 64;                       // total K chunks
    constexpr int LCH = NCH / SPLITK;                 // chunks this CTA
    constexpr int SST = 72;                           // smem row stride (elems)
    constexpr int TILEB = 128 * SST * 2;              // 18432 B per operand tile
    constexpr int STG   = 2 * TILEB;                  // 36864 B per stage {A,B}
    constexpr int STAGES = 3;

    const __half* __restrict__ A = SIG ? g_x1  : g_l1;
    const __half* __restrict__ B = SIG ? g_gw1 : g_z1;

    const int tid = threadIdx.x, wid = tid >> 5, lane = tid & 31;
    const int m0 = blockIdx.y * 128, n0 = blockIdx.x * 128;
    const int zc = blockIdx.z;
    const int c0 = zc * LCH;
    const int wm = (wid & 1) * 64, wn = (wid >> 1) * 32;
    const uint32_t sb = smem_u32(smem);

    const __half* gA = A + (size_t)m0 * K;
    const __half* gB = B + (size_t)n0 * K;

    float acc[4][4][4];
    #pragma unroll
    for (int i = 0; i < 4; i++)
        #pragma unroll
        for (int j = 0; j < 4; j++)
            #pragma unroll
            for (int k = 0; k < 4; k++) acc[i][j][k] = 0.f;

    // ldmatrix lane addressing
    const int arow  = wm + (lane & 15);
    const int ahalf = (lane >> 4) * 8;
    const int brow  = wn + (lane & 7) + ((lane >> 4) << 3);
    const int bkof  = ((lane >> 3) & 1) * 8;

    // G2S: 4 threads/row (64 rows/pass, 2 passes); quad = (tid&3) + 4*i
    const int lrow = tid >> 2, lq = tid & 3;

    auto load_chunk = [&](int c, int s) {
        const int koff = c * 64;
        const uint32_t base = sb + s * STG;
        #pragma unroll
        for (int rg = 0; rg < 2; rg++) {
            const int row = lrow + rg * 64;
            const __half* pa = gA + (size_t)row * K + koff;
            const __half* pb = gB + (size_t)row * K + koff;
            #pragma unroll
            for (int i = 0; i < 2; i++) {
                const int q = lq + 4 * i;
                uint32_t so = (uint32_t)(row * SST + q * 8) * 2;
                CP16(base + so,         pa + q * 8);
                CP16(base + TILEB + so, pb + q * 8);
            }
        }
        CPCOMMIT();
    };

    load_chunk(c0, 0);
    if (LCH > 1) load_chunk(c0 + 1, 1);
    for (int lc = 0; lc < LCH; lc++) {
        const int s = lc % STAGES;
        if (lc == LCH - 1) { CPWAIT(0); }             // last chunk: drain ALL
        else               { CPWAIT(1); }             // steady: 1 newer pending
        __syncthreads();
        if (lc + STAGES - 1 < LCH)                    // refill freed stage
            load_chunk(c0 + lc + STAGES - 1, (lc + STAGES - 1) % STAGES);

        const uint32_t aB = sb + s * STG;
        const uint32_t bB = aB + TILEB;
        #pragma unroll
        for (int kk = 0; kk < 4; kk++) {
            uint32_t a[4][4], b[2][4];
            #pragma unroll
            for (int mt = 0; mt < 4; mt++)
                ldm4(a[mt], aB + (uint32_t)((arow + mt * 16) * SST + kk * 16 + ahalf) * 2);
            #pragma unroll
            for (int np = 0; np < 2; np++)
                ldm4(b[np], bB + (uint32_t)((brow + np * 16) * SST + kk * 16 + bkof) * 2);
            #pragma unroll
            for (int mt = 0; mt < 4; mt++)
                #pragma unroll
                for (int nt = 0; nt < 4; nt++)
                    mma16816(acc[mt][nt], a[mt], &b[nt >> 1][(nt & 1) * 2]);
        }
        __syncthreads();                              // protect stage reuse
    }

    // epilogue
    const int mg = m0 + wm + (lane >> 2);
    const int cg = (lane & 3) * 2;
    #pragma unroll
    for (int mt = 0; mt < 4; mt++) {
        const int m = mg + mt * 16;
        #pragma unroll
        for (int nt = 0; nt < 4; nt++) {
            const int n = n0 + wn + nt * 8 + cg;
            float* ac = acc[mt][nt];
            if (SIG) {
                float b0 = (n     < GATES) ? gb[n]     : 0.f;
                float b1 = (n + 1 < GATES) ? gb[n + 1] : 0.f;
                float2 v0{1.f / (1.f + __expf(-(ac[0] + b0))),
                          1.f / (1.f + __expf(-(ac[1] + b1)))};
                float2 v1{1.f / (1.f + __expf(-(ac[2] + b0))),
                          1.f / (1.f + __expf(-(ac[3] + b1)))};
                *reinterpret_cast<float2*>(&g_gat[(size_t)m * GPAD + n])       = v0;
                *reinterpret_cast<float2*>(&g_gat[(size_t)(m + 8) * GPAD + n]) = v1;
            } else if (SPLITK > 1) {
                float* pp = &g_part[(size_t)zc * BATCH * OUTF];
                *reinterpret_cast<float2*>(&pp[(size_t)m * OUTF + n])       = float2{ac[0], ac[1]};
                *reinterpret_cast<float2*>(&pp[(size_t)(m + 8) * OUTF + n]) = float2{ac[2], ac[3]};
            } else {
                *reinterpret_cast<float2*>(&outp[(size_t)m * OUTF + n])       = float2{ac[0], ac[1]};
                *reinterpret_cast<float2*>(&outp[(size_t)(m + 8) * OUTF + n]) = float2{ac[2], ac[3]};
            }
        }
    }
}

// ---------------- split-K reduce: out = sum of SPLK3 partials ---------------
__global__ __launch_bounds__(256) void k_red(float* __restrict__ out) {
    int i = blockIdx.x * 256 + threadIdx.x;           // float4 index
    float4 a = reinterpret_cast<const float4*>(g_part)[i];
    #pragma unroll
    for (int p = 1; p < SPLK3; p++) {
        float4 b = reinterpret_cast<const float4*>(g_part + (size_t)p * BATCH * OUTF)[i];
        a.x += b.x; a.y += b.y; a.z += b.z; a.w += b.w;
    }
    reinterpret_cast<float4*>(out)[i] = a;
}

// ---------------- K2: leaf densities -> single fp16 -------------------------
__global__ __launch_bounds__(256) void k_leaf() {
    __shared__ __align__(16) float bufA[8][512];
    __shared__ __align__(16) float bufB[8][1024];
    const int w    = threadIdx.x >> 5;
    const int lane = threadIdx.x & 31;
    const int row  = blockIdx.x * 8 + w;
    const float* __restrict__ gr = &g_gat[(size_t)row * GPAD];

    if (lane == 0) bufB[w][0] = 1.f;
    __syncwarp();

    for (int d = 0; d < 10; d++) {
        const int n = 1 << d, start = n - 1;
        float* src = (d & 1) ? bufA[w] : bufB[w];
        float* dst = (d & 1) ? bufB[w] : bufA[w];
        for (int i = lane; i < n; i += 32) {
            float p = src[i], g = gr[start + i];
            dst[2 * i]     = p * g;
            dst[2 * i + 1] = p * (1.f - g);
        }
        __syncwarp();
    }

    const size_t base = (size_t)row * LEAVES;
    #pragma unroll
    for (int j = 0; j < 8; j++) {
        int i = (j * 32 + lane) * 4;
        float4 v = *reinterpret_cast<float4*>(&bufB[w][i]);
        *reinterpret_cast<__half2*>(&g_l1[base + i])     = __half2{__float2half_rn(v.x), __float2half_rn(v.y)};
        *reinterpret_cast<__half2*>(&g_l1[base + i + 2]) = __half2{__float2half_rn(v.z), __float2half_rn(v.w)};
    }
}

// ---------------------------------------------------------------------------
extern "C" void kernel_launch(void* const* d_in, const int* in_sizes, int n_in,
                              void* d_out, int out_size) {
    const float* x  = (const float*)d_in[0];   // [16384, 256]
    const float* gw = (const float*)d_in[1];   // [256, 1023]
    const float* gb = (const float*)d_in[2];   // [1023]
    const float* z  = (const float*)d_in[3];   // [128, 1024]
    float* out = (float*)d_out;                // [16384, 128]

    const int SMEM_SZ = 3 * 36864;             // 110592 B (3 stages x {A,B})
    cudaFuncSetAttribute((const void*)k_mma<INF, true, 1>,
                         cudaFuncAttributeMaxDynamicSharedMemorySize, SMEM_SZ);
    cudaFuncSetAttribute((const void*)k_mma<LEAVES, false, SPLK3>,
                         cudaFuncAttributeMaxDynamicSharedMemorySize, SMEM_SZ);

    conv_x  <<<(BATCH * INF / 4) / 256, 256>>>(x);
    conv_gwt<<<(INF * GPAD) / 256, 256>>>(gw);
    conv_z  <<<(OUTF * LEAVES / 4) / 256, 256>>>(z);

    k_mma<INF, true, 1><<<dim3(GPAD / 128, BATCH / 128, 1), 256, SMEM_SZ>>>(gb, out);
    k_leaf<<<BATCH / 8, 256>>>();
    k_mma<LEAVES, false, SPLK3><<<dim3(1, BATCH / 128, SPLK3), 256, SMEM_SZ>>>(gb, out);
    k_red<<<(BATCH * OUTF / 4) / 256, 256>>>(out);
}